// round 3
// baseline (speedup 1.0000x reference)
#include <cuda_runtime.h>
#include <cuda_bf16.h>
#include <cstdint>

// Problem constants
#define CC    64
#define HWSZ  4096
#define NTOK  131072
#define KCOD  512
#define EPSF  1e-5f

// Output layout (concatenated reference outputs, all float32)
#define OUT_ELEMS  8388608
#define LOSS_OFF   8388608
#define UNIQ_OFF   8388609
#define CB_OFF     8388610

// -------- device scratch --------
__device__ float g_counts[KCOD];
__device__ float g_sums[KCOD * CC];
__device__ float g_loss;

// -------- helpers --------
__device__ __forceinline__ void red4(float* p, float a, float b, float c, float d) {
    asm volatile("red.global.add.v4.f32 [%0], {%1, %2, %3, %4};"
                 :: "l"(p), "f"(a), "f"(b), "f"(c), "f"(d) : "memory");
}
__device__ __forceinline__ float warp_red(float v) {
    #pragma unroll
    for (int o = 16; o; o >>= 1) v += __shfl_xor_sync(0xffffffffu, v, o);
    return v;
}

// ============================================================
// Kernel 0: zero accumulators
// ============================================================
__global__ void k_zero() {
    int i = blockIdx.x * 512 + threadIdx.x;
    if (i < KCOD * CC) g_sums[i] = 0.0f;
    if (i < KCOD)      g_counts[i] = 0.0f;
    if (i == 0)        g_loss = 0.0f;
}

// ============================================================
// Kernel 1: fused assign + quantized output + loss + counts/sums
// 512 CTAs x 256 threads, 1 token/thread (x in registers),
// full codebook resident in smem (128KB) + q (2KB). 1 CTA/SM.
// Mainloop is plain scalar FFMA (full-rate on sm_100a).
// ============================================================
#define SMEM_ASSIGN (KCOD * CC * 4 + KCOD * 4)   // 133120 B

__global__ __launch_bounds__(256, 1)
void k_assign(const float* __restrict__ x,
              const float* __restrict__ cb,
              float* __restrict__ out) {
    extern __shared__ float smem[];
    float* es = smem;               // [512][64]
    float* qs = es + KCOD * CC;     // [512]
    __shared__ float red_s[8];

    const int tid  = threadIdx.x;
    const int lane = tid & 31;

    // ---- load full codebook to smem (coalesced float4) ----
    float4* es4 = (float4*)es;
    const float4* cb4 = (const float4*)cb;
    #pragma unroll
    for (int i = 0; i < 32; ++i)            // 32 * 256 = 8192 float4
        es4[i * 256 + tid] = cb4[i * 256 + tid];
    __syncthreads();

    // ---- q[k] = 0.5*|e_k|^2  (rotated reads to dodge bank degeneracy) ----
    #pragma unroll
    for (int r = 0; r < 2; ++r) {
        int k = tid + r * 256;
        const float4* row = (const float4*)(es + k * CC);
        float s = 0.0f;
        #pragma unroll
        for (int j = 0; j < 16; ++j) {
            float4 v = row[(j + lane) & 15];
            s += v.x*v.x + v.y*v.y + v.z*v.z + v.w*v.w;
        }
        qs[k] = 0.5f * s;
    }
    __syncthreads();

    // ---- load this thread's token x into registers (coalesced) ----
    const int blk = blockIdx.x;
    const int b   = blk >> 4;                       // 16 CTAs per image
    const int p   = ((blk & 15) << 8) + tid;        // position within H*W
    const float* xb = x + ((size_t)b << 18) + p;    // b*64*4096 + p

    float xr[64];
    #pragma unroll
    for (int c = 0; c < 64; ++c) xr[c] = xb[(size_t)c << 12];

    float xsq = 0.0f;
    #pragma unroll
    for (int c = 0; c < 64; ++c) xsq += xr[c] * xr[c];

    // ---- mainloop: 512 codes, 8-code register tile, scalar FFMA ----
    float best = 3.4e38f;
    int   bi   = 0;
    const float4* esr = (const float4*)es;          // 16 float4 per code row

    for (int k0 = 0; k0 < KCOD; k0 += 8) {
        float acc[8];
        #pragma unroll
        for (int kk = 0; kk < 8; ++kk) acc[kk] = 0.0f;

        #pragma unroll
        for (int c4 = 0; c4 < 16; ++c4) {
            #pragma unroll
            for (int kk = 0; kk < 8; ++kk) {
                float4 e = esr[(k0 + kk) * 16 + c4];   // warp-broadcast LDS.128
                acc[kk] += xr[4*c4 + 0] * e.x;
                acc[kk] += xr[4*c4 + 1] * e.y;
                acc[kk] += xr[4*c4 + 2] * e.z;
                acc[kk] += xr[4*c4 + 3] * e.w;
            }
        }
        #pragma unroll
        for (int kk = 0; kk < 8; ++kk) {
            float d = qs[k0 + kk] - acc[kk];
            if (d < best) { best = d; bi = k0 + kk; }   // strict < keeps first min
        }
    }

    // ---- commitment loss partial: |x-e|^2 = |x|^2 + 2*best ----
    float lsum = warp_red(xsq + 2.0f * best);
    if (lane == 0) red_s[tid >> 5] = lsum;
    __syncthreads();
    if (tid == 0) {
        float a = 0.0f;
        #pragma unroll
        for (int i = 0; i < 8; ++i) a += red_s[i];
        atomicAdd(&g_loss, a);
    }

    // ---- counts + segment sums (vector global reductions) ----
    atomicAdd(&g_counts[bi], 1.0f);
    float* srow = g_sums + bi * CC;
    #pragma unroll
    for (int i = 0; i < 16; ++i)
        red4(srow + i * 4, xr[4*i], xr[4*i+1], xr[4*i+2], xr[4*i+3]);

    // ---- quantized output: gather chosen row from smem, coalesced STG ----
    float* ob = out + ((size_t)b << 18) + p;
    const float4* erow = (const float4*)(es + (bi << 6));
    #pragma unroll
    for (int j = 0; j < 16; ++j) {
        float4 v = erow[j];
        ob[(size_t)(4*j + 0) << 12] = v.x;
        ob[(size_t)(4*j + 1) << 12] = v.y;
        ob[(size_t)(4*j + 2) << 12] = v.z;
        ob[(size_t)(4*j + 3) << 12] = v.w;
    }
}

// ============================================================
// Kernel 2: EMA update + smoothing + new codebook + scalars
// grid 64 x 512; each CTA redundantly reduces counts (cheap),
// then writes its 512-element slice of the codebook.
// ============================================================
__global__ __launch_bounds__(512)
void k_final(const float* __restrict__ ema_cs,
             const float* __restrict__ ema_w,
             float* __restrict__ out) {
    __shared__ float sm[KCOD];
    __shared__ float rn[16], ru[16];
    __shared__ float s_n, s_u;

    const int t = threadIdx.x;
    float cnt = g_counts[t];
    float ncs = 0.99f * ema_cs[t] + 0.01f * cnt;

    float nv = warp_red(ncs);
    float uv = warp_red(cnt > 0.0f ? 1.0f : 0.0f);
    if ((t & 31) == 0) { rn[t >> 5] = nv; ru[t >> 5] = uv; }
    __syncthreads();
    if (t == 0) {
        float a = 0.0f, u = 0.0f;
        #pragma unroll
        for (int i = 0; i < 16; ++i) { a += rn[i]; u += ru[i]; }
        s_n = a; s_u = u;
    }
    __syncthreads();

    sm[t] = (ncs + EPSF) / (s_n + (float)KCOD * EPSF) * s_n;
    __syncthreads();

    int i = blockIdx.x * 512 + t;                 // 64 CTAs x 512 = 32768
    float nw = 0.99f * ema_w[i] + 0.01f * g_sums[i];
    out[CB_OFF + i] = nw / sm[i >> 6];

    if (blockIdx.x == 0 && t == 0) {
        out[LOSS_OFF] = g_loss * (1.0f / (float)OUT_ELEMS);
        out[UNIQ_OFF] = s_u;
    }
}

// ============================================================
extern "C" void kernel_launch(void* const* d_in, const int* in_sizes, int n_in,
                              void* d_out, int out_size) {
    const float* x   = (const float*)d_in[0];
    const float* cb  = (const float*)d_in[1];
    const float* ecs = (const float*)d_in[2];
    const float* ew  = (const float*)d_in[3];
    float* out = (float*)d_out;

    cudaFuncSetAttribute(k_assign, cudaFuncAttributeMaxDynamicSharedMemorySize, SMEM_ASSIGN);

    k_zero<<<65, 512>>>();
    k_assign<<<NTOK / 256, 256, SMEM_ASSIGN>>>(x, cb, out);
    k_final<<<64, 512>>>(ecs, ew, out);
}

// round 6
// speedup vs baseline: 1.4592x; 1.4592x over previous
#include <cuda_runtime.h>
#include <cuda_bf16.h>
#include <cstdint>

// Problem constants
#define CC    64
#define HWSZ  4096
#define NTOK  131072
#define KCOD  512
#define EPSF  1e-5f

// Output layout
#define OUT_ELEMS  8388608
#define LOSS_OFF   8388608
#define UNIQ_OFF   8388609
#define CB_OFF     8388610

// -------- device scratch --------
__device__ float g_counts[KCOD];
__device__ float g_sums[KCOD * CC];
__device__ float g_loss;

// -------- helpers --------
__device__ __forceinline__ uint32_t f2tf32(float f) {
    uint32_t u;
    asm("cvt.rna.tf32.f32 %0, %1;" : "=r"(u) : "f"(f));
    return u;
}
__device__ __forceinline__ void red4(float* p, float a, float b, float c, float d) {
    asm volatile("red.global.add.v4.f32 [%0], {%1, %2, %3, %4};"
                 :: "l"(p), "f"(a), "f"(b), "f"(c), "f"(d) : "memory");
}
__device__ __forceinline__ float warp_red(float v) {
    #pragma unroll
    for (int o = 16; o; o >>= 1) v += __shfl_xor_sync(0xffffffffu, v, o);
    return v;
}
__device__ __forceinline__ void mma8(float* d, const uint32_t* a, uint32_t b0, uint32_t b1) {
    asm volatile(
        "mma.sync.aligned.m16n8k8.row.col.f32.tf32.tf32.f32 "
        "{%0,%1,%2,%3}, {%4,%5,%6,%7}, {%8,%9}, {%0,%1,%2,%3};"
        : "+f"(d[0]), "+f"(d[1]), "+f"(d[2]), "+f"(d[3])
        : "r"(a[0]), "r"(a[1]), "r"(a[2]), "r"(a[3]), "r"(b0), "r"(b1));
}

// ---- smem layout (float indices) ----
// stride 68: fragment lanes hit banks (4*gr + cq) % 32 -> all distinct
#define STR    68
#define S_XHI  0
#define S_XLO  (S_XHI + 128 * STR)         // 8704
#define S_EHI  (S_XLO + 128 * STR)         // 17408
#define S_ELO  (S_EHI + 128 * STR)         // 26112
#define S_QS   (S_ELO + 128 * STR)         // 34816
#define S_SB   (S_QS + KCOD)               // 35328  (best dist per token)
#define S_RED  (S_SB + 128)                // 35456
#define S_SIDX (S_RED + 8)                 // 35464  (int)
#define SMEM_FLOATS (S_SIDX + 128)         // 35592
#define SMEM_ASSIGN (SMEM_FLOATS * 4)      // 142368 B

// ============================================================
// Kernel 0: zero accumulators
// ============================================================
__global__ void k_zero() {
    int i = blockIdx.x * 512 + threadIdx.x;
    if (i < KCOD * CC) g_sums[i] = 0.0f;
    if (i < KCOD)      g_counts[i] = 0.0f;
    if (i == 0)        g_loss = 0.0f;
}

// ============================================================
// Kernel 1: tf32 mma.sync assign + fused epilogue
// 1024 CTAs x 256 threads; 128 tokens/CTA; 8 warps x 16-token m-tiles;
// codebook streamed in 4 chunks of 128 codes (hi/lo tf32 in smem).
// ============================================================
__global__ __launch_bounds__(256, 1)
void k_assign(const float* __restrict__ x,
              const float* __restrict__ cb,
              float* __restrict__ out) {
    extern __shared__ float sm[];
    uint32_t* smu = (uint32_t*)sm;
    int* sidx = (int*)(sm + S_SIDX);

    const int tid  = threadIdx.x;
    const int wid  = tid >> 5;
    const int lane = tid & 31;
    const int gr   = lane >> 2;     // 0..7
    const int cq   = lane & 3;      // 0..3

    const int blk = blockIdx.x;
    const int b   = blk >> 5;                 // 32 CTAs per image
    const int p0  = (blk & 31) << 7;          // token base in H*W
    const float* xbase = x + ((size_t)b << 18);

    // ---- stage x: token = tid&127 (row), channels half per thread ----
    {
        const int tok = tid & 127;
        const int c0  = (tid >> 7) * 32;
        const float* xp = xbase + ((size_t)c0 << 12) + p0 + tok;
        #pragma unroll
        for (int j = 0; j < 32; ++j) {
            float v = xp[(size_t)j << 12];
            uint32_t h = f2tf32(v);
            float r = v - __uint_as_float(h);
            smu[S_XHI + tok * STR + c0 + j] = h;
            smu[S_XLO + tok * STR + c0 + j] = f2tf32(r);
        }
    }
    // ---- stage qs = 0.5*|e_k|^2 (2 codes/thread) ----
    #pragma unroll
    for (int r = 0; r < 2; ++r) {
        int k = tid + r * 256;
        const float4* row = (const float4*)(cb + (size_t)k * CC);
        float s = 0.0f;
        #pragma unroll
        for (int j = 0; j < 16; ++j) {
            float4 v = __ldg(row + j);
            s += v.x * v.x + v.y * v.y + v.z * v.z + v.w * v.w;
        }
        sm[S_QS + k] = 0.5f * s;
    }
    __syncthreads();

    // ---- preload A fragments (16 tokens per warp, all 8 k-steps, hi+lo) ----
    const int m0 = wid << 4;
    const int ra = m0 + gr, rb = ra + 8;
    uint32_t ahi[8][4], alo[8][4];
    #pragma unroll
    for (int k = 0; k < 8; ++k) {
        int cA = k * 8 + cq;
        ahi[k][0] = smu[S_XHI + ra * STR + cA];
        ahi[k][1] = smu[S_XHI + rb * STR + cA];
        ahi[k][2] = smu[S_XHI + ra * STR + cA + 4];
        ahi[k][3] = smu[S_XHI + rb * STR + cA + 4];
        alo[k][0] = smu[S_XLO + ra * STR + cA];
        alo[k][1] = smu[S_XLO + rb * STR + cA];
        alo[k][2] = smu[S_XLO + ra * STR + cA + 4];
        alo[k][3] = smu[S_XLO + rb * STR + cA + 4];
    }

    float best0 = 3.4e38f, best1 = 3.4e38f;
    int   bi0 = 0, bi1 = 0;

    // ---- chunk loop: 4 x 128 codes ----
    for (int chk = 0; chk < 4; ++chk) {
        __syncthreads();   // previous chunk fully consumed
        {   // stage e chunk: row = tid/2 (code), half channels per thread
            const int row = tid >> 1;
            const int c0  = (tid & 1) * 32;
            const float4* src = (const float4*)(cb + (size_t)(chk * 128 + row) * CC + c0);
            #pragma unroll
            for (int j = 0; j < 8; ++j) {
                float4 v = __ldg(src + j);
                float vv[4] = {v.x, v.y, v.z, v.w};
                #pragma unroll
                for (int t = 0; t < 4; ++t) {
                    uint32_t h = f2tf32(vv[t]);
                    float r = vv[t] - __uint_as_float(h);
                    smu[S_EHI + row * STR + c0 + 4 * j + t] = h;
                    smu[S_ELO + row * STR + c0 + 4 * j + t] = f2tf32(r);
                }
            }
        }
        __syncthreads();

        // 4 groups x 4 n-tiles (32 codes each)
        for (int g = 0; g < 4; ++g) {
            float acc[4][4];
            #pragma unroll
            for (int t = 0; t < 4; ++t)
                #pragma unroll
                for (int i = 0; i < 4; ++i) acc[t][i] = 0.0f;

            const int n0 = g * 32;
            #pragma unroll
            for (int k = 0; k < 8; ++k) {
                const int cB = k * 8 + cq;
                #pragma unroll
                for (int t = 0; t < 4; ++t) {
                    int nb = n0 + t * 8 + gr;
                    uint32_t bh0 = smu[S_EHI + nb * STR + cB];
                    uint32_t bh1 = smu[S_EHI + nb * STR + cB + 4];
                    uint32_t bl0 = smu[S_ELO + nb * STR + cB];
                    uint32_t bl1 = smu[S_ELO + nb * STR + cB + 4];
                    mma8(acc[t], ahi[k], bh0, bh1);   // hi*hi
                    mma8(acc[t], alo[k], bh0, bh1);   // lo*hi
                    mma8(acc[t], ahi[k], bl0, bl1);   // hi*lo
                }
            }
            #pragma unroll
            for (int t = 0; t < 4; ++t) {
                int kb = chk * 128 + n0 + t * 8 + 2 * cq;
                float q0 = sm[S_QS + kb], q1 = sm[S_QS + kb + 1];
                float d00 = q0 - acc[t][0], d01 = q1 - acc[t][1];
                float d10 = q0 - acc[t][2], d11 = q1 - acc[t][3];
                if (d00 < best0) { best0 = d00; bi0 = kb; }
                if (d01 < best0) { best0 = d01; bi0 = kb + 1; }
                if (d10 < best1) { best1 = d10; bi1 = kb; }
                if (d11 < best1) { best1 = d11; bi1 = kb + 1; }
            }
        }
    }

    // ---- quad argmin reduce (lanes sharing a token: xor 1, xor 2) ----
    #pragma unroll
    for (int m = 1; m <= 2; m <<= 1) {
        float ob0 = __shfl_xor_sync(0xffffffffu, best0, m);
        int   oi0 = __shfl_xor_sync(0xffffffffu, bi0,   m);
        if (ob0 < best0 || (ob0 == best0 && oi0 < bi0)) { best0 = ob0; bi0 = oi0; }
        float ob1 = __shfl_xor_sync(0xffffffffu, best1, m);
        int   oi1 = __shfl_xor_sync(0xffffffffu, bi1,   m);
        if (ob1 < best1 || (ob1 == best1 && oi1 < bi1)) { best1 = ob1; bi1 = oi1; }
    }
    if (cq == 0) {
        sidx[ra] = bi0; sm[S_SB + ra] = best0;
        sidx[rb] = bi1; sm[S_SB + rb] = best1;
    }
    __syncthreads();

    // ---- loss + counts + segment sums (threads 0..127, x re-read L2-hot) ----
    if (tid < 128) {
        const float* xq = xbase + p0 + tid;
        float xr[64];
        #pragma unroll
        for (int c = 0; c < 64; ++c) xr[c] = xq[(size_t)c << 12];
        float xsq = 0.0f;
        #pragma unroll
        for (int c = 0; c < 64; ++c) xsq += xr[c] * xr[c];

        int bi = sidx[tid];
        atomicAdd(&g_counts[bi], 1.0f);
        float* srow = g_sums + bi * CC;
        #pragma unroll
        for (int i = 0; i < 16; ++i)
            red4(srow + i * 4, xr[4*i], xr[4*i+1], xr[4*i+2], xr[4*i+3]);

        float lsum = warp_red(xsq + 2.0f * sm[S_SB + tid]);
        if (lane == 0) sm[S_RED + wid] = lsum;
    }
    __syncthreads();
    if (tid == 0)
        atomicAdd(&g_loss, sm[S_RED+0] + sm[S_RED+1] + sm[S_RED+2] + sm[S_RED+3]);

    // ---- quantized output: 2 threads/token, coalesced STG ----
    {
        const int tok   = tid & 127;
        const int chalf = tid >> 7;
        const int bi    = sidx[tok];
        float* ob = out + ((size_t)b << 18) + p0 + tok;
        const float4* er = (const float4*)(cb + (size_t)bi * CC) + chalf * 8;
        #pragma unroll
        for (int j = 0; j < 8; ++j) {
            float4 v = __ldg(er + j);
            int c = chalf * 32 + 4 * j;
            ob[(size_t)(c + 0) << 12] = v.x;
            ob[(size_t)(c + 1) << 12] = v.y;
            ob[(size_t)(c + 2) << 12] = v.z;
            ob[(size_t)(c + 3) << 12] = v.w;
        }
    }
}

// ============================================================
// Kernel 2: EMA update + smoothing + new codebook + scalars
// ============================================================
__global__ __launch_bounds__(512)
void k_final(const float* __restrict__ ema_cs,
             const float* __restrict__ ema_w,
             float* __restrict__ out) {
    __shared__ float smc[KCOD];
    __shared__ float rn[16], ru[16];
    __shared__ float s_n, s_u;

    const int t = threadIdx.x;
    float cnt = g_counts[t];
    float ncs = 0.99f * ema_cs[t] + 0.01f * cnt;

    float nv = warp_red(ncs);
    float uv = warp_red(cnt > 0.0f ? 1.0f : 0.0f);
    if ((t & 31) == 0) { rn[t >> 5] = nv; ru[t >> 5] = uv; }
    __syncthreads();
    if (t == 0) {
        float a = 0.0f, u = 0.0f;
        #pragma unroll
        for (int i = 0; i < 16; ++i) { a += rn[i]; u += ru[i]; }
        s_n = a; s_u = u;
    }
    __syncthreads();

    smc[t] = (ncs + EPSF) / (s_n + (float)KCOD * EPSF) * s_n;
    __syncthreads();

    int i = blockIdx.x * 512 + t;
    float nw = 0.99f * ema_w[i] + 0.01f * g_sums[i];
    out[CB_OFF + i] = nw / smc[i >> 6];

    if (blockIdx.x == 0 && t == 0) {
        out[LOSS_OFF] = g_loss * (1.0f / (float)OUT_ELEMS);
        out[UNIQ_OFF] = s_u;
    }
}

// ============================================================
extern "C" void kernel_launch(void* const* d_in, const int* in_sizes, int n_in,
                              void* d_out, int out_size) {
    const float* x   = (const float*)d_in[0];
    const float* cb  = (const float*)d_in[1];
    const float* ecs = (const float*)d_in[2];
    const float* ew  = (const float*)d_in[3];
    float* out = (float*)d_out;

    cudaFuncSetAttribute(k_assign, cudaFuncAttributeMaxDynamicSharedMemorySize, SMEM_ASSIGN);

    k_zero<<<65, 512>>>();
    k_assign<<<NTOK / 128, 256, SMEM_ASSIGN>>>(x, cb, out);
    k_final<<<64, 512>>>(ecs, ew, out);
}